// round 2
// baseline (speedup 1.0000x reference)
#include <cuda_runtime.h>
#include <math.h>

#define NN 100000
#define HH 20
#define EHID 64
#define EOUT 10

// ---- device scratch (no allocations allowed) ----
__device__ float g_sumw[(size_t)NN * HH];   // 8 MB  : per-node sum_w rows [N,20]
__device__ float g_sd[NN];                  // 400KB : per-node sum of distances
__device__ float g_c[EOUT];                 // collapsed MLP: mlp_out = d*c + b2 (when b1==0)
__device__ int   g_b1zero;

// ---------------------------------------------------------------------------
// setup: compute c[j] = sum_k relu(W1[k]) * W2[k,j]; detect b1 == 0
// ---------------------------------------------------------------------------
__global__ void k_setup(const float* __restrict__ W1,
                        const float* __restrict__ b1,
                        const float* __restrict__ W2) {
    int j = threadIdx.x;
    if (j == 0) {
        int z = 1;
        for (int k = 0; k < EHID; k++)
            if (b1[k] != 0.0f) { z = 0; break; }
        g_b1zero = z;
    }
    if (j < EOUT) {
        float s = 0.0f;
        for (int k = 0; k < EHID; k++) {
            float w = W1[k];
            s = fmaf(w > 0.0f ? w : 0.0f, W2[k * EOUT + j], s);
        }
        g_c[j] = s;
    }
}

// ---------------------------------------------------------------------------
// zero scratch
// ---------------------------------------------------------------------------
__global__ void k_zero(int n_cnt) {
    int i = blockIdx.x * blockDim.x + threadIdx.x;
    int tot = n_cnt * HH;
    if (i < tot) g_sumw[i] = 0.0f;
    if (i < n_cnt) g_sd[i] = 0.0f;
}

// ---------------------------------------------------------------------------
// pass 1: per-edge accumulation of sum_w building blocks
//   fast path (b1==0): count[src][bucket]+=1 ; sd[src]+=d     (2 scalar REDs)
//   slow path: full MLP per edge, vector REDs for mlp part
// ---------------------------------------------------------------------------
__global__ void k_pass1(const int* __restrict__ ei,
                        const float* __restrict__ attr,
                        const float* __restrict__ W1,
                        const float* __restrict__ b1,
                        const float* __restrict__ W2,
                        int e_cnt) {
    int e = blockIdx.x * blockDim.x + threadIdx.x;
    if (e >= e_cnt) return;
    int src = ei[e];
    float d = attr[e];
    int idx = (int)(d * 10.0f);
    idx = idx < 0 ? 0 : (idx > 9 ? 9 : idx);

    atomicAdd(&g_sumw[(size_t)src * HH + idx], 1.0f);

    if (g_b1zero) {
        atomicAdd(&g_sd[src], d);
    } else {
        float m[EOUT];
#pragma unroll
        for (int j = 0; j < EOUT; j++) m[j] = 0.0f;
        for (int k = 0; k < EHID; k++) {
            float h = fmaf(d, __ldg(W1 + k), __ldg(b1 + k));
            h = h > 0.0f ? h : 0.0f;
#pragma unroll
            for (int j = 0; j < EOUT; j++)
                m[j] = fmaf(h, __ldg(W2 + k * EOUT + j), m[j]);
        }
        float* p = g_sumw + (size_t)src * HH + 10;
        asm volatile("red.global.add.v2.f32 [%0], {%1,%2};"
                     :: "l"(p), "f"(m[0]), "f"(m[1]) : "memory");
        asm volatile("red.global.add.v4.f32 [%0], {%1,%2,%3,%4};"
                     :: "l"(p + 2), "f"(m[2]), "f"(m[3]), "f"(m[4]), "f"(m[5]) : "memory");
        asm volatile("red.global.add.v4.f32 [%0], {%1,%2,%3,%4};"
                     :: "l"(p + 6), "f"(m[6]), "f"(m[7]), "f"(m[8]), "f"(m[9]) : "memory");
    }
}

// ---------------------------------------------------------------------------
// materialize sum_w mlp half: sum_w[n][10+j] = c[j]*sd[n] + b2[j]*deg[n]
// (slow path: += b2[j]*deg on top of the per-edge accumulated h@W2 sums)
// ---------------------------------------------------------------------------
__global__ void k_mat(const float* __restrict__ b2, int n_cnt) {
    int n = blockIdx.x * blockDim.x + threadIdx.x;
    if (n >= n_cnt) return;
    float* row = g_sumw + (size_t)n * HH;
    float deg = 0.0f;
#pragma unroll
    for (int i = 0; i < 10; i++) deg += row[i];
    float sd = g_sd[n];
    int bz = g_b1zero;
#pragma unroll
    for (int j = 0; j < EOUT; j++) {
        float base = bz ? g_c[j] * sd : row[10 + j];
        row[10 + j] = fmaf(__ldg(b2 + j), deg, base);
    }
}

// ---------------------------------------------------------------------------
// pass 2: per-edge message computation, scatter into d_out[n,1,:] via red.v4
// ---------------------------------------------------------------------------
__device__ __forceinline__ float edge_msg(float eac, float sw, float hx, float hd,
                                          float a, float oma, float b) {
    float w = (sw != 0.0f) ? __fdividef(eac, sw) : 0.01f;
    float v = fabsf(fmaf(a, hx, -oma * hd));
    float rho = __powf(v, b);   // |v|^b via LG2/EX2; v==0 -> 0
    return rho * w;
}

__global__ void __launch_bounds__(256)
k_pass2(const int* __restrict__ ei,
        const float* __restrict__ attr,
        const float* __restrict__ x,
        const float* __restrict__ pa,
        const float* __restrict__ pb,
        const float* __restrict__ W1,
        const float* __restrict__ b1,
        const float* __restrict__ W2,
        const float* __restrict__ b2,
        float* __restrict__ out,
        int e_cnt) {
    int e = blockIdx.x * blockDim.x + threadIdx.x;
    if (e >= e_cnt) return;
    int src = ei[e];
    int dst = ei[e_cnt + e];
    float d = attr[e];
    int idx = (int)(d * 10.0f);
    idx = idx < 0 ? 0 : (idx > 9 ? 9 : idx);

    float a   = __ldg(pa);
    float b   = __ldg(pb);
    float oma = 1.0f - a;

    // mlp half of eac
    float mlp[EOUT];
    if (g_b1zero) {
#pragma unroll
        for (int j = 0; j < EOUT; j++) mlp[j] = fmaf(d, g_c[j], __ldg(b2 + j));
    } else {
#pragma unroll
        for (int j = 0; j < EOUT; j++) mlp[j] = __ldg(b2 + j);
        for (int k = 0; k < EHID; k++) {
            float h = fmaf(d, __ldg(W1 + k), __ldg(b1 + k));
            h = h > 0.0f ? h : 0.0f;
#pragma unroll
            for (int j = 0; j < EOUT; j++)
                mlp[j] = fmaf(h, __ldg(W2 + k * EOUT + j), mlp[j]);
        }
    }

    const float4* swp = (const float4*)(g_sumw + (size_t)src * HH);
    const float4* xs  = (const float4*)(x + (size_t)src * 2 * HH);   // x[src,0,:]
    const float4* xd  = (const float4*)(x + (size_t)dst * 2 * HH);   // x[dst,0,:]
    float* op = out + (size_t)src * 2 * HH + HH;                     // d_out[src,1,:]

#pragma unroll
    for (int q = 0; q < 5; q++) {
        float4 sw4 = swp[q];
        float4 s4  = xs[q];
        float4 d4  = xd[q];
        int j0 = q * 4;
        float e0 = (j0 + 0 < 10) ? ((j0 + 0 == idx) ? 1.0f : 0.0f) : mlp[j0 - 10 + 0];
        float e1 = (j0 + 1 < 10) ? ((j0 + 1 == idx) ? 1.0f : 0.0f) : mlp[j0 - 10 + 1];
        float e2 = (j0 + 2 < 10) ? ((j0 + 2 == idx) ? 1.0f : 0.0f) : mlp[j0 - 10 + 2];
        float e3 = (j0 + 3 < 10) ? ((j0 + 3 == idx) ? 1.0f : 0.0f) : mlp[j0 - 10 + 3];
        float m0 = edge_msg(e0, sw4.x, s4.x, d4.x, a, oma, b);
        float m1 = edge_msg(e1, sw4.y, s4.y, d4.y, a, oma, b);
        float m2 = edge_msg(e2, sw4.z, s4.z, d4.z, a, oma, b);
        float m3 = edge_msg(e3, sw4.w, s4.w, d4.w, a, oma, b);
        asm volatile("red.global.add.v4.f32 [%0], {%1,%2,%3,%4};"
                     :: "l"(op + q * 4), "f"(m0), "f"(m1), "f"(m2), "f"(m3) : "memory");
    }
}

// ---------------------------------------------------------------------------
// pass 3: node update  out0 = sigmoid(x0 @ g1^T + sf @ g2^T + bias)
// ---------------------------------------------------------------------------
__global__ void __launch_bounds__(256)
k_pass3(const float* __restrict__ x,
        const float* __restrict__ g1,
        const float* __restrict__ g2,
        const float* __restrict__ bias,
        float* __restrict__ out,
        int n_cnt) {
    __shared__ float s1[HH * HH], s2[HH * HH], sb[HH];
    for (int i = threadIdx.x; i < HH * HH; i += blockDim.x) {
        s1[i] = g1[i];
        s2[i] = g2[i];
    }
    if (threadIdx.x < HH) sb[threadIdx.x] = bias[threadIdx.x];
    __syncthreads();

    int n = blockIdx.x * blockDim.x + threadIdx.x;
    if (n >= n_cnt) return;

    float x0[HH], sf[HH];
    const float4* xp = (const float4*)(x + (size_t)n * 2 * HH);
    const float4* sp = (const float4*)(out + (size_t)n * 2 * HH + HH);
#pragma unroll
    for (int q = 0; q < 5; q++) {
        float4 v = xp[q];
        x0[q * 4 + 0] = v.x; x0[q * 4 + 1] = v.y; x0[q * 4 + 2] = v.z; x0[q * 4 + 3] = v.w;
        float4 s = sp[q];
        sf[q * 4 + 0] = s.x; sf[q * 4 + 1] = s.y; sf[q * 4 + 2] = s.z; sf[q * 4 + 3] = s.w;
    }

    float* o = out + (size_t)n * 2 * HH;
#pragma unroll
    for (int i = 0; i < HH; i++) {
        float acc = sb[i];
#pragma unroll
        for (int j = 0; j < HH; j++) {
            acc = fmaf(s1[i * HH + j], x0[j], acc);
            acc = fmaf(s2[i * HH + j], sf[j], acc);
        }
        o[i] = __fdividef(1.0f, 1.0f + __expf(-acc));
    }
}

// ---------------------------------------------------------------------------
extern "C" void kernel_launch(void* const* d_in, const int* in_sizes, int n_in,
                              void* d_out, int out_size) {
    const float* x    = (const float*)d_in[0];
    const int*   ei   = (const int*)d_in[1];
    const float* attr = (const float*)d_in[2];
    const float* a    = (const float*)d_in[3];
    const float* b    = (const float*)d_in[4];
    const float* g1   = (const float*)d_in[5];
    const float* g2   = (const float*)d_in[6];
    const float* bias = (const float*)d_in[7];
    const float* W1   = (const float*)d_in[8];
    const float* b1   = (const float*)d_in[9];
    const float* W2   = (const float*)d_in[10];
    const float* b2   = (const float*)d_in[11];

    int e_cnt = in_sizes[1] / 2;          // edge_index is [2, E]
    int n_cnt = in_sizes[0] / (2 * HH);   // x is [N, 2, H]
    float* out = (float*)d_out;

    cudaMemsetAsync(out, 0, (size_t)out_size * sizeof(float));
    k_setup<<<1, 64>>>(W1, b1, W2);
    int zt = n_cnt * HH;
    k_zero<<<(zt + 255) / 256, 256>>>(n_cnt);
    k_pass1<<<(e_cnt + 255) / 256, 256>>>(ei, attr, W1, b1, W2, e_cnt);
    k_mat<<<(n_cnt + 255) / 256, 256>>>(b2, n_cnt);
    k_pass2<<<(e_cnt + 255) / 256, 256>>>(ei, attr, x, a, b, W1, b1, W2, b2, out, e_cnt);
    k_pass3<<<(n_cnt + 255) / 256, 256>>>(x, g1, g2, bias, out, n_cnt);
}

// round 3
// speedup vs baseline: 1.2270x; 1.2270x over previous
#include <cuda_runtime.h>
#include <math.h>

#define NN 100000
#define EE 3200000
#define HH 20
#define EHID 64
#define EOUT 10

// ---- device scratch (static, no runtime allocation) ----
__device__ int   g_deg[NN];     // node degree (as src)
__device__ int   g_off[NN];     // CSR exclusive offsets
__device__ int   g_cur[NN];     // scatter cursors
__device__ int   g_bsum[512];   // scan block sums
__device__ int   g_dst[EE];     // CSR: dst per edge
__device__ float g_dist[EE];    // CSR: distance per edge
__device__ float g_c[EOUT];     // collapsed MLP (b1==0): mlp_out = d*c + b2
__device__ int   g_b1zero;

// ---------------------------------------------------------------------------
__global__ void k_setup(const float* __restrict__ W1,
                        const float* __restrict__ b1,
                        const float* __restrict__ W2) {
    int j = threadIdx.x;
    if (j == 0) {
        int z = 1;
        for (int k = 0; k < EHID; k++)
            if (b1[k] != 0.0f) { z = 0; break; }
        g_b1zero = z;
    }
    if (j < EOUT) {
        float s = 0.0f;
        for (int k = 0; k < EHID; k++) {
            float w = W1[k];
            s = fmaf(w > 0.0f ? w : 0.0f, W2[k * EOUT + j], s);
        }
        g_c[j] = s;
    }
}

__global__ void k_zerodeg(int n_cnt) {
    int i = blockIdx.x * blockDim.x + threadIdx.x;
    if (i < n_cnt) g_deg[i] = 0;
}

__global__ void k_hist(const int* __restrict__ ei, int e_cnt) {
    int e = blockIdx.x * blockDim.x + threadIdx.x;
    if (e < e_cnt) atomicAdd(&g_deg[ei[e]], 1);
}

// -- scan: 3 small kernels -------------------------------------------------
__global__ void k_scan1(int n_cnt) {
    __shared__ int s[256];
    int t = threadIdx.x;
    int i = blockIdx.x * 256 + t;
    int v = (i < n_cnt) ? g_deg[i] : 0;
    s[t] = v;
    __syncthreads();
#pragma unroll
    for (int o = 1; o < 256; o <<= 1) {
        int add = (t >= o) ? s[t - o] : 0;
        __syncthreads();
        s[t] += add;
        __syncthreads();
    }
    if (i < n_cnt) g_off[i] = s[t];          // inclusive within block
    if (t == 255) g_bsum[blockIdx.x] = s[255];
}

__global__ void k_scan2(int nb) {
    __shared__ int s[512];
    int t = threadIdx.x;
    int v = (t < nb) ? g_bsum[t] : 0;
    s[t] = v;
    __syncthreads();
#pragma unroll
    for (int o = 1; o < 512; o <<= 1) {
        int add = (t >= o) ? s[t - o] : 0;
        __syncthreads();
        s[t] += add;
        __syncthreads();
    }
    if (t < nb) g_bsum[t] = s[t] - v;         // exclusive block offsets
}

__global__ void k_scan3(int n_cnt) {
    int i = blockIdx.x * blockDim.x + threadIdx.x;
    if (i >= n_cnt) return;
    int excl = g_off[i] - g_deg[i] + g_bsum[i >> 8];
    g_off[i] = excl;
    g_cur[i] = excl;
}

__global__ void k_scatter(const int* __restrict__ ei,
                          const float* __restrict__ attr, int e_cnt) {
    int e = blockIdx.x * blockDim.x + threadIdx.x;
    if (e >= e_cnt) return;
    int src = ei[e];
    int p = atomicAdd(&g_cur[src], 1);
    g_dst[p] = ei[e_cnt + e];
    g_dist[p] = attr[e];
}

// ---------------------------------------------------------------------------
// mega: per-node fused pipeline (sum_w in regs, messages, node update)
// ---------------------------------------------------------------------------
__global__ void __launch_bounds__(256)
k_mega(const float* __restrict__ x,
       const float* __restrict__ pa, const float* __restrict__ pb,
       const float* __restrict__ g1, const float* __restrict__ g2,
       const float* __restrict__ bias,
       const float* __restrict__ W1, const float* __restrict__ b1,
       const float* __restrict__ W2, const float* __restrict__ b2,
       float* __restrict__ out, int n_cnt) {
    __shared__ float s1[HH * HH], s2[HH * HH], sb[HH];
    for (int i = threadIdx.x; i < HH * HH; i += blockDim.x) {
        s1[i] = g1[i];
        s2[i] = g2[i];
    }
    if (threadIdx.x < HH) sb[threadIdx.x] = bias[threadIdx.x];
    __syncthreads();

    int n = blockIdx.x * blockDim.x + threadIdx.x;
    if (n >= n_cnt) return;

    const int deg = g_deg[n];
    const int off = g_off[n];
    const float aa = __ldg(pa);
    const float bb = __ldg(pb);
    const float oma = 1.0f - aa;
    const int bz = g_b1zero;

    // ---- phase 1: bucket counts + sum of distances (+ slow-path mlp sums)
    int cnt[10];
    float msum[10];
#pragma unroll
    for (int j = 0; j < 10; j++) { cnt[j] = 0; msum[j] = 0.0f; }
    float sd = 0.0f;
    for (int i = 0; i < deg; i++) {
        float d = g_dist[off + i];
        sd += d;
        int idx = (int)(d * 10.0f);
        idx = idx < 0 ? 0 : (idx > 9 ? 9 : idx);
#pragma unroll
        for (int j = 0; j < 10; j++) cnt[j] += (idx == j) ? 1 : 0;
        if (!bz) {
            for (int k = 0; k < EHID; k++) {
                float h = fmaf(d, __ldg(W1 + k), __ldg(b1 + k));
                h = h > 0.0f ? h : 0.0f;
#pragma unroll
                for (int j = 0; j < 10; j++)
                    msum[j] = fmaf(h, __ldg(W2 + k * EOUT + j), msum[j]);
            }
        }
    }

    // ---- per-node hoisted weights / reciprocals
    float rcnt[10], wb[10], rsw[10], wbm[10];
    float fdeg = (float)deg;
#pragma unroll
    for (int j = 0; j < 10; j++) {
        rcnt[j] = cnt[j] > 0 ? __fdividef(1.0f, (float)cnt[j]) : 0.0f;
        wb[j]   = cnt[j] > 0 ? 0.0f : 0.01f;
        float sw = bz ? fmaf(g_c[j], sd, __ldg(b2 + j) * fdeg)
                      : (msum[j] + __ldg(b2 + j) * fdeg);
        rsw[j] = (sw != 0.0f) ? __fdividef(1.0f, sw) : 0.0f;
        wbm[j] = (sw != 0.0f) ? 0.0f : 1.0f;   // flag: sw==0 -> const 0.01 weight
    }

    // ---- node's own feature row (x[n,0,:]) loaded ONCE
    float xs0[HH];
    {
        const float4* xp = (const float4*)(x + (size_t)n * 2 * HH);
#pragma unroll
        for (int q = 0; q < 5; q++) {
            float4 v = xp[q];
            xs0[q * 4 + 0] = v.x; xs0[q * 4 + 1] = v.y;
            xs0[q * 4 + 2] = v.z; xs0[q * 4 + 3] = v.w;
        }
    }

    // ---- phase 2: edge loop, accumulate messages in registers
    float sfo[10];   // one-hot columns
    float sfP[10];   // mlp: sum rho*d    (fast)  | direct sf (slow path)
    float sfQ[10];   // mlp: sum rho
#pragma unroll
    for (int j = 0; j < 10; j++) { sfo[j] = 0.0f; sfP[j] = 0.0f; sfQ[j] = 0.0f; }

    for (int i = 0; i < deg; i++) {
        int dst = g_dst[off + i];
        float d = g_dist[off + i];
        int idx = (int)(d * 10.0f);
        idx = idx < 0 ? 0 : (idx > 9 ? 9 : idx);

        float xr[HH];
        const float4* xq = (const float4*)(x + (size_t)dst * 2 * HH);
#pragma unroll
        for (int q = 0; q < 5; q++) {
            float4 v = xq[q];
            xr[q * 4 + 0] = v.x; xr[q * 4 + 1] = v.y;
            xr[q * 4 + 2] = v.z; xr[q * 4 + 3] = v.w;
        }

        if (bz) {
#pragma unroll
            for (int j = 0; j < 10; j++) {
                // one-hot column j
                float t0 = oma * xr[j];
                float v0 = fabsf(fmaf(aa, xs0[j], -t0));
                float r0 = __powf(v0, bb);
                float w0 = (j == idx) ? rcnt[j] : wb[j];
                sfo[j] = fmaf(r0, w0, sfo[j]);
                // mlp column 10+j : accumulate rho and rho*d
                float t1 = oma * xr[10 + j];
                float v1 = fabsf(fmaf(aa, xs0[10 + j], -t1));
                float r1 = __powf(v1, bb);
                sfQ[j] += r1;
                sfP[j] = fmaf(r1, d, sfP[j]);
            }
        } else {
            // slow fallback: full MLP per edge
            float eac[10];
#pragma unroll
            for (int j = 0; j < 10; j++) eac[j] = __ldg(b2 + j);
            for (int k = 0; k < EHID; k++) {
                float h = fmaf(d, __ldg(W1 + k), __ldg(b1 + k));
                h = h > 0.0f ? h : 0.0f;
#pragma unroll
                for (int j = 0; j < 10; j++)
                    eac[j] = fmaf(h, __ldg(W2 + k * EOUT + j), eac[j]);
            }
#pragma unroll
            for (int j = 0; j < 10; j++) {
                float t0 = oma * xr[j];
                float v0 = fabsf(fmaf(aa, xs0[j], -t0));
                float r0 = __powf(v0, bb);
                float w0 = (j == idx) ? rcnt[j] : wb[j];
                sfo[j] = fmaf(r0, w0, sfo[j]);
                float t1 = oma * xr[10 + j];
                float v1 = fabsf(fmaf(aa, xs0[10 + j], -t1));
                float r1 = __powf(v1, bb);
                float w1 = (wbm[j] > 0.0f) ? 0.01f : eac[j] * rsw[j];
                sfP[j] = fmaf(r1, w1, sfP[j]);
            }
        }
    }

    // ---- finalize sum_features
    float sf[HH];
#pragma unroll
    for (int j = 0; j < 10; j++) {
        sf[j] = sfo[j];
        if (bz) {
            float base = fmaf(g_c[j], sfP[j], __ldg(b2 + j) * sfQ[j]) * rsw[j];
            sf[10 + j] = (wbm[j] > 0.0f) ? 0.01f * sfQ[j] : base;
        } else {
            sf[10 + j] = sfP[j];
        }
    }

    // ---- write sum_features to out[n,1,:]
    float* o = out + (size_t)n * 2 * HH;
    float4* o4 = (float4*)(o + HH);
#pragma unroll
    for (int q = 0; q < 5; q++)
        o4[q] = make_float4(sf[q * 4 + 0], sf[q * 4 + 1], sf[q * 4 + 2], sf[q * 4 + 3]);

    // ---- fused node update: out[n,0,:] = sigmoid(x0 @ g1^T + sf @ g2^T + bias)
#pragma unroll
    for (int i = 0; i < HH; i++) {
        float acc = sb[i];
#pragma unroll
        for (int j = 0; j < HH; j++) {
            acc = fmaf(s1[i * HH + j], xs0[j], acc);
            acc = fmaf(s2[i * HH + j], sf[j], acc);
        }
        o[i] = __fdividef(1.0f, 1.0f + __expf(-acc));
    }
}

// ---------------------------------------------------------------------------
extern "C" void kernel_launch(void* const* d_in, const int* in_sizes, int n_in,
                              void* d_out, int out_size) {
    const float* x    = (const float*)d_in[0];
    const int*   ei   = (const int*)d_in[1];
    const float* attr = (const float*)d_in[2];
    const float* a    = (const float*)d_in[3];
    const float* b    = (const float*)d_in[4];
    const float* g1   = (const float*)d_in[5];
    const float* g2   = (const float*)d_in[6];
    const float* bias = (const float*)d_in[7];
    const float* W1   = (const float*)d_in[8];
    const float* b1   = (const float*)d_in[9];
    const float* W2   = (const float*)d_in[10];
    const float* b2   = (const float*)d_in[11];

    int e_cnt = in_sizes[1] / 2;          // edge_index is [2, E]
    int n_cnt = in_sizes[0] / (2 * HH);   // x is [N, 2, H]
    float* out = (float*)d_out;

    int nb = (n_cnt + 255) / 256;
    int eb = (e_cnt + 255) / 256;

    k_setup<<<1, 64>>>(W1, b1, W2);
    k_zerodeg<<<nb, 256>>>(n_cnt);
    k_hist<<<eb, 256>>>(ei, e_cnt);
    k_scan1<<<nb, 256>>>(n_cnt);
    k_scan2<<<1, 512>>>(nb);
    k_scan3<<<nb, 256>>>(n_cnt);
    k_scatter<<<eb, 256>>>(ei, attr, e_cnt);
    k_mega<<<nb, 256>>>(x, a, b, g1, g2, bias, W1, b1, W2, b2, out, n_cnt);
}

// round 4
// speedup vs baseline: 1.2470x; 1.0163x over previous
#include <cuda_runtime.h>
#include <math.h>

#define NN 100000
#define EE 3200000
#define HH 20
#define EHID 64
#define EOUT 10

// ---- device scratch (static, no runtime allocation) ----
__device__ int   g_deg[NN];     // node degree (as src)
__device__ int   g_off[NN];     // CSR exclusive offsets
__device__ int   g_cur[NN];     // scatter cursors
__device__ int   g_bsum[512];   // scan block sums
__device__ int2  g_pair[EE];    // CSR: (dst, dist-bits) per edge
__device__ float g_c[EOUT];     // collapsed MLP (b1==0): mlp_out = d*c + b2
__device__ int   g_b1zero;

// ---------------------------------------------------------------------------
__global__ void k_setup(const float* __restrict__ W1,
                        const float* __restrict__ b1,
                        const float* __restrict__ W2) {
    int j = threadIdx.x;
    if (j == 0) {
        int z = 1;
        for (int k = 0; k < EHID; k++)
            if (b1[k] != 0.0f) { z = 0; break; }
        g_b1zero = z;
    }
    if (j < EOUT) {
        float s = 0.0f;
        for (int k = 0; k < EHID; k++) {
            float w = W1[k];
            s = fmaf(w > 0.0f ? w : 0.0f, W2[k * EOUT + j], s);
        }
        g_c[j] = s;
    }
}

__global__ void k_zerodeg(int n_cnt) {
    int i = blockIdx.x * blockDim.x + threadIdx.x;
    if (i < n_cnt) g_deg[i] = 0;
}

__global__ void k_hist(const int* __restrict__ ei, int e_cnt) {
    int e = blockIdx.x * blockDim.x + threadIdx.x;
    if (e < e_cnt) atomicAdd(&g_deg[ei[e]], 1);
}

// -- scan: 3 small kernels ---------------------------------------------------
__global__ void k_scan1(int n_cnt) {
    __shared__ int s[256];
    int t = threadIdx.x;
    int i = blockIdx.x * 256 + t;
    int v = (i < n_cnt) ? g_deg[i] : 0;
    s[t] = v;
    __syncthreads();
#pragma unroll
    for (int o = 1; o < 256; o <<= 1) {
        int add = (t >= o) ? s[t - o] : 0;
        __syncthreads();
        s[t] += add;
        __syncthreads();
    }
    if (i < n_cnt) g_off[i] = s[t];          // inclusive within block
    if (t == 255) g_bsum[blockIdx.x] = s[255];
}

__global__ void k_scan2(int nb) {
    __shared__ int s[512];
    int t = threadIdx.x;
    int v = (t < nb) ? g_bsum[t] : 0;
    s[t] = v;
    __syncthreads();
#pragma unroll
    for (int o = 1; o < 512; o <<= 1) {
        int add = (t >= o) ? s[t - o] : 0;
        __syncthreads();
        s[t] += add;
        __syncthreads();
    }
    if (t < nb) g_bsum[t] = s[t] - v;         // exclusive block offsets
}

__global__ void k_scan3(int n_cnt) {
    int i = blockIdx.x * blockDim.x + threadIdx.x;
    if (i >= n_cnt) return;
    int excl = g_off[i] - g_deg[i] + g_bsum[i >> 8];
    g_off[i] = excl;
    g_cur[i] = excl;
}

__global__ void k_scatter(const int* __restrict__ ei,
                          const float* __restrict__ attr, int e_cnt) {
    int e = blockIdx.x * blockDim.x + threadIdx.x;
    if (e >= e_cnt) return;
    int src = ei[e];
    int p = atomicAdd(&g_cur[src], 1);
    g_pair[p] = make_int2(ei[e_cnt + e], __float_as_int(attr[e]));
}

// ---------------------------------------------------------------------------
// mega: warp-per-node, lane-per-column, single pass over edges
// ---------------------------------------------------------------------------
__global__ void __launch_bounds__(256)
k_mega(const float* __restrict__ x,
       const float* __restrict__ pa, const float* __restrict__ pb,
       const float* __restrict__ g1, const float* __restrict__ g2,
       const float* __restrict__ bias,
       const float* __restrict__ W1, const float* __restrict__ b1,
       const float* __restrict__ W2, const float* __restrict__ b2,
       float* __restrict__ out, int n_cnt) {
    __shared__ float s1[HH * 21], s2[HH * 21], sb[HH];
    for (int i = threadIdx.x; i < HH * HH; i += blockDim.x) {
        int r = i / HH, cix = i % HH;
        s1[r * 21 + cix] = g1[i];
        s2[r * 21 + cix] = g2[i];
    }
    if (threadIdx.x < HH) sb[threadIdx.x] = bias[threadIdx.x];
    __syncthreads();

    const int warp = threadIdx.x >> 5;
    const int lane = threadIdx.x & 31;
    const int n = blockIdx.x * 8 + warp;
    if (n >= n_cnt) return;

    const int deg = g_deg[n];
    const int off = g_off[n];
    const float aa = __ldg(pa);
    const float bbp = __ldg(pb);
    const float oma = 1.0f - aa;
    const int bz = g_b1zero;

    const bool active = lane < HH;
    const bool isOH = lane < 10;        // one-hot column
    const int mcol = lane - 10;         // mlp column index (lane >= 10)

    const float x0l = active ? __ldg(x + (size_t)n * 2 * HH + lane) : 0.0f;
    const float cl  = (active && !isOH) ? g_c[mcol] : 0.0f;
    const float b2l = (active && !isOH) ? __ldg(b2 + mcol) : 0.0f;

    // per-lane accumulators (lane owns one column)
    float A = 0.0f;   // one-hot: sum rho over matching edges
    float B = 0.0f;   // one-hot: sum rho over all edges
    float P = 0.0f;   // mlp fast: sum rho*d   | mlp slow: sum rho*eac
    float Q = 0.0f;   // mlp: sum rho
    float V = 0.0f;   // mlp slow: sum eac
    float sd = 0.0f;  // sum of distances (replicated in every lane)
    int cnt = 0;      // one-hot bucket count

    const int2* pair = g_pair + off;

    if (bz) {
#pragma unroll 4
        for (int i = 0; i < deg; i++) {
            int2 pr = pair[i];                       // uniform broadcast load
            float d = __int_as_float(pr.y);
            sd += d;
            int idx = (int)(d * 10.0f);
            idx = idx > 9 ? 9 : (idx < 0 ? 0 : idx);
            float xr = active ? __ldg(x + (size_t)pr.x * 2 * HH + lane) : 0.0f;
            float v = fabsf(fmaf(aa, x0l, -oma * xr));
            float rho = __powf(v, bbp);              // |v|^b ; v==0 -> 0
            if (isOH) {
                B += rho;
                bool m = (idx == lane);
                cnt += m ? 1 : 0;
                A += m ? rho : 0.0f;
            } else {
                Q += rho;
                P = fmaf(rho, d, P);
            }
        }
    } else {
        for (int i = 0; i < deg; i++) {
            int2 pr = pair[i];
            float d = __int_as_float(pr.y);
            sd += d;
            int idx = (int)(d * 10.0f);
            idx = idx > 9 ? 9 : (idx < 0 ? 0 : idx);
            float xr = active ? __ldg(x + (size_t)pr.x * 2 * HH + lane) : 0.0f;
            float v = fabsf(fmaf(aa, x0l, -oma * xr));
            float rho = __powf(v, bbp);
            if (isOH) {
                B += rho;
                bool m = (idx == lane);
                cnt += m ? 1 : 0;
                A += m ? rho : 0.0f;
            } else {
                float eac = b2l;
                for (int k = 0; k < EHID; k++) {
                    float h = fmaf(d, __ldg(W1 + k), __ldg(b1 + k));
                    h = h > 0.0f ? h : 0.0f;
                    eac = fmaf(h, __ldg(W2 + k * EOUT + mcol), eac);
                }
                P = fmaf(rho, eac, P);
                V += eac;
                Q += rho;
            }
        }
    }

    // ---- finalize this lane's sum_features column
    float sf;
    if (isOH) {
        sf = (cnt > 0) ? A * __fdividef(1.0f, (float)cnt) : 0.01f * B;
    } else {
        float Vv = bz ? fmaf(cl, sd, b2l * (float)deg) : V;
        float Uu = bz ? fmaf(cl, P, b2l * Q) : P;
        sf = (Vv != 0.0f) ? Uu * __fdividef(1.0f, Vv) : 0.01f * Q;
    }

    float* o = out + (size_t)n * 2 * HH;
    if (active) o[HH + lane] = sf;               // out[n,1,:]

    // ---- node update: out[n,0,i] = sigmoid(sum_j g1[i,j]x0[j] + g2[i,j]sf[j] + bias[i])
    int li = active ? lane : 0;                   // clamp smem row for idle lanes
    float acc = active ? sb[li] : 0.0f;
#pragma unroll
    for (int j = 0; j < HH; j++) {
        float bx = __shfl_sync(0xFFFFFFFFu, x0l, j);
        float bs = __shfl_sync(0xFFFFFFFFu, sf, j);
        acc = fmaf(s1[li * 21 + j], bx, acc);
        acc = fmaf(s2[li * 21 + j], bs, acc);
    }
    if (active) o[lane] = __fdividef(1.0f, 1.0f + __expf(-acc));
}

// ---------------------------------------------------------------------------
extern "C" void kernel_launch(void* const* d_in, const int* in_sizes, int n_in,
                              void* d_out, int out_size) {
    const float* x    = (const float*)d_in[0];
    const int*   ei   = (const int*)d_in[1];
    const float* attr = (const float*)d_in[2];
    const float* a    = (const float*)d_in[3];
    const float* b    = (const float*)d_in[4];
    const float* g1   = (const float*)d_in[5];
    const float* g2   = (const float*)d_in[6];
    const float* bias = (const float*)d_in[7];
    const float* W1   = (const float*)d_in[8];
    const float* b1   = (const float*)d_in[9];
    const float* W2   = (const float*)d_in[10];
    const float* b2   = (const float*)d_in[11];

    int e_cnt = in_sizes[1] / 2;          // edge_index is [2, E]
    int n_cnt = in_sizes[0] / (2 * HH);   // x is [N, 2, H]
    float* out = (float*)d_out;

    int nb = (n_cnt + 255) / 256;
    int eb = (e_cnt + 255) / 256;

    k_setup<<<1, 64>>>(W1, b1, W2);
    k_zerodeg<<<nb, 256>>>(n_cnt);
    k_hist<<<eb, 256>>>(ei, e_cnt);
    k_scan1<<<nb, 256>>>(n_cnt);
    k_scan2<<<1, 512>>>(nb);
    k_scan3<<<nb, 256>>>(n_cnt);
    k_scatter<<<eb, 256>>>(ei, attr, e_cnt);
    k_mega<<<(n_cnt + 7) / 8, 256>>>(x, a, b, g1, g2, bias, W1, b1, W2, b2, out, n_cnt);
}

// round 5
// speedup vs baseline: 1.3137x; 1.0535x over previous
#include <cuda_runtime.h>
#include <math.h>

#define NN 100000
#define EE 3200000
#define HH 20
#define EHID 64
#define EOUT 10
#define SCANB 512   // max scan blocks

// ---- device scratch (static; zero-initialized at module load) ----
__device__ int   g_deg[NN];                 // node degree (zeroed by k_mega each call)
__device__ int   g_cnt2[NN];                // scatter cursors (zeroed by k_mega each call)
__device__ int   g_off[NN];                 // CSR exclusive offsets
__device__ unsigned long long g_flag[SCANB];// lookback flags (generation-tagged, never reset)
__device__ unsigned long long g_gen;        // generation counter
__device__ int2  g_pair[EE];                // CSR: (dst, dist-bits)
__device__ float g_c[EOUT];                 // collapsed MLP (b1==0): mlp_out = d*c + b2
__device__ int   g_b1zero;

// ---------------------------------------------------------------------------
// launch 1: histogram + setup + generation bump
// ---------------------------------------------------------------------------
__global__ void k_histsetup(const int* __restrict__ ei,
                            const float* __restrict__ W1,
                            const float* __restrict__ b1,
                            const float* __restrict__ W2, int e_cnt) {
    if (blockIdx.x == 0) {
        int j = threadIdx.x;
        if (j == 0) {
            g_gen = g_gen + 1;
            int z = 1;
            for (int k = 0; k < EHID; k++)
                if (b1[k] != 0.0f) { z = 0; break; }
            g_b1zero = z;
        }
        if (j < EOUT) {
            float s = 0.0f;
            for (int k = 0; k < EHID; k++) {
                float w = W1[k];
                s = fmaf(w > 0.0f ? w : 0.0f, W2[k * EOUT + j], s);
            }
            g_c[j] = s;
        }
    }
    int e = blockIdx.x * blockDim.x + threadIdx.x;
    if (e < e_cnt) atomicAdd(&g_deg[ei[e]], 1);
}

// ---------------------------------------------------------------------------
// launch 2: single-kernel exclusive scan (decoupled lookback, gen-tagged)
// ---------------------------------------------------------------------------
__global__ void __launch_bounds__(256) k_scan(int n_cnt) {
    __shared__ int s[256];
    __shared__ int sPre;
    int t = threadIdx.x, bid = blockIdx.x;
    int i = bid * 256 + t;
    int v = (i < n_cnt) ? g_deg[i] : 0;
    s[t] = v;
    __syncthreads();
#pragma unroll
    for (int o = 1; o < 256; o <<= 1) {
        int add = (t >= o) ? s[t - o] : 0;
        __syncthreads();
        s[t] += add;
        __syncthreads();
    }
    int total = s[255];

    unsigned long long gen = g_gen;
    unsigned long long wantA = gen * 4 + 1, wantP = gen * 4 + 2;

    if (t == 0) {
        unsigned long long st = (bid == 0) ? wantP : wantA;
        atomicExch(&g_flag[bid], (st << 32) | (unsigned long long)(unsigned)total);
        if (bid == 0) sPre = 0;
    }
    if (bid > 0 && t < 32) {
        int sum = 0;
        int base = bid - 1;
        for (;;) {
            int p = base - t;
            unsigned long long w = 0;
            if (p >= 0) {
                volatile unsigned long long* vp = g_flag + p;
                unsigned long long hi;
                do { w = *vp; hi = w >> 32; } while (hi != wantA && hi != wantP);
            }
            bool isP = (p >= 0) && ((w >> 32) == wantP);
            unsigned mask = __ballot_sync(0xFFFFFFFFu, isP);
            if (mask) {
                int firstP = __ffs((int)mask) - 1;
                if (t <= firstP) sum += (int)(unsigned)w;
                break;
            }
            sum += (int)(unsigned)w;   // all are aggregates (p<0 lanes contribute 0)
            base -= 32;
        }
#pragma unroll
        for (int o = 16; o; o >>= 1) sum += __shfl_down_sync(0xFFFFFFFFu, sum, o);
        if (t == 0) {
            sPre = sum;
            atomicExch(&g_flag[bid],
                       (wantP << 32) | (unsigned long long)(unsigned)(sum + total));
        }
    }
    __syncthreads();
    if (i < n_cnt) g_off[i] = sPre + s[t] - v;   // global exclusive offset
}

// ---------------------------------------------------------------------------
// launch 3: scatter (dst, dist) into CSR order
// ---------------------------------------------------------------------------
__global__ void k_scatter(const int* __restrict__ ei,
                          const float* __restrict__ attr, int e_cnt) {
    int e = blockIdx.x * blockDim.x + threadIdx.x;
    if (e >= e_cnt) return;
    int src = ei[e];
    int p = g_off[src] + atomicAdd(&g_cnt2[src], 1);
    g_pair[p] = make_int2(ei[e_cnt + e], __float_as_int(attr[e]));
}

// ---------------------------------------------------------------------------
// launch 4 (PROFILED SLOT): warp-per-node fused pipeline + scratch re-zero
// ---------------------------------------------------------------------------
__global__ void __launch_bounds__(256)
k_mega(const float* __restrict__ x,
       const float* __restrict__ pa, const float* __restrict__ pb,
       const float* __restrict__ g1, const float* __restrict__ g2,
       const float* __restrict__ bias,
       const float* __restrict__ W1, const float* __restrict__ b1,
       const float* __restrict__ W2, const float* __restrict__ b2,
       float* __restrict__ out, int n_cnt) {
    __shared__ float s1[HH * 21], s2[HH * 21], sb[HH];
    for (int i = threadIdx.x; i < HH * HH; i += blockDim.x) {
        int r = i / HH, cix = i % HH;
        s1[r * 21 + cix] = g1[i];
        s2[r * 21 + cix] = g2[i];
    }
    if (threadIdx.x < HH) sb[threadIdx.x] = bias[threadIdx.x];
    __syncthreads();

    const int warp = threadIdx.x >> 5;
    const int lane = threadIdx.x & 31;
    const int n = blockIdx.x * 8 + warp;
    if (n >= n_cnt) return;

    const int deg = g_deg[n];
    const int off = g_off[n];
    const float aa = __ldg(pa);
    const float bbp = __ldg(pb);
    const float oma = 1.0f - aa;
    const int bz = g_b1zero;

    const bool active = lane < HH;
    const bool isOH = lane < 10;
    const int mcol = lane - 10;

    const float x0l = active ? __ldg(x + (size_t)n * 2 * HH + lane) : 0.0f;
    const float ax0 = aa * x0l;
    const float cl  = (active && !isOH) ? g_c[mcol] : 0.0f;
    const float b2l = (active && !isOH) ? __ldg(b2 + mcol) : 0.0f;

    float A = 0.0f, B = 0.0f;   // one-hot: matching rho-sum / total rho-sum
    float P = 0.0f, Q = 0.0f;   // mlp: sum rho*d (or rho*eac) / sum rho
    float V = 0.0f;             // mlp slow path: sum eac
    float sd = 0.0f;
    int cnt = 0;

    const int2* pair = g_pair + off;

    if (bz) {
#pragma unroll 4
        for (int i = 0; i < deg; i++) {
            int2 pr = pair[i];
            float d = __int_as_float(pr.y);
            sd += d;
            int idx = (int)(d * 10.0f);
            idx = idx > 9 ? 9 : idx;
            float xr = active ? __ldg(x + (size_t)pr.x * 2 * HH + lane) : 0.0f;
            float v = fabsf(fmaf(-oma, xr, ax0));
            float rho = __powf(v, bbp);
            if (isOH) {
                B += rho;
                bool m = (idx == lane);
                cnt += m ? 1 : 0;
                A += m ? rho : 0.0f;
            } else {
                Q += rho;
                P = fmaf(rho, d, P);
            }
        }
    } else {
        for (int i = 0; i < deg; i++) {
            int2 pr = pair[i];
            float d = __int_as_float(pr.y);
            sd += d;
            int idx = (int)(d * 10.0f);
            idx = idx > 9 ? 9 : idx;
            float xr = active ? __ldg(x + (size_t)pr.x * 2 * HH + lane) : 0.0f;
            float v = fabsf(fmaf(-oma, xr, ax0));
            float rho = __powf(v, bbp);
            if (isOH) {
                B += rho;
                bool m = (idx == lane);
                cnt += m ? 1 : 0;
                A += m ? rho : 0.0f;
            } else {
                float eac = b2l;
                for (int k = 0; k < EHID; k++) {
                    float h = fmaf(d, __ldg(W1 + k), __ldg(b1 + k));
                    h = h > 0.0f ? h : 0.0f;
                    eac = fmaf(h, __ldg(W2 + k * EOUT + mcol), eac);
                }
                P = fmaf(rho, eac, P);
                V += eac;
                Q += rho;
            }
        }
    }

    // finalize this lane's sum_features column
    float sf;
    if (isOH) {
        sf = (cnt > 0) ? A * __fdividef(1.0f, (float)cnt) : 0.01f * B;
    } else {
        float Vv = bz ? fmaf(cl, sd, b2l * (float)deg) : V;
        float Uu = bz ? fmaf(cl, P, b2l * Q) : P;
        sf = (Vv != 0.0f) ? Uu * __fdividef(1.0f, Vv) : 0.01f * Q;
    }

    float* o = out + (size_t)n * 2 * HH;
    if (active) o[HH + lane] = sf;               // out[n,1,:]

    // node update: out[n,0,i] = sigmoid(g1[i,:]·x0 + g2[i,:]·sf + bias[i])
    int li = active ? lane : 0;
    float acc = active ? sb[li] : 0.0f;
#pragma unroll
    for (int j = 0; j < HH; j++) {
        float bx = __shfl_sync(0xFFFFFFFFu, x0l, j);
        float bs = __shfl_sync(0xFFFFFFFFu, sf, j);
        acc = fmaf(s1[li * 21 + j], bx, acc);
        acc = fmaf(s2[li * 21 + j], bs, acc);
    }
    if (active) o[lane] = __fdividef(1.0f, 1.0f + __expf(-acc));

    // restore scratch invariant for the next execution
    if (lane == 0) {
        g_deg[n] = 0;
        g_cnt2[n] = 0;
    }
}

// ---------------------------------------------------------------------------
extern "C" void kernel_launch(void* const* d_in, const int* in_sizes, int n_in,
                              void* d_out, int out_size) {
    const float* x    = (const float*)d_in[0];
    const int*   ei   = (const int*)d_in[1];
    const float* attr = (const float*)d_in[2];
    const float* a    = (const float*)d_in[3];
    const float* b    = (const float*)d_in[4];
    const float* g1   = (const float*)d_in[5];
    const float* g2   = (const float*)d_in[6];
    const float* bias = (const float*)d_in[7];
    const float* W1   = (const float*)d_in[8];
    const float* b1   = (const float*)d_in[9];
    const float* W2   = (const float*)d_in[10];
    const float* b2   = (const float*)d_in[11];

    int e_cnt = in_sizes[1] / 2;          // edge_index is [2, E]
    int n_cnt = in_sizes[0] / (2 * HH);   // x is [N, 2, H]
    float* out = (float*)d_out;

    int eb = (e_cnt + 255) / 256;
    int sb_blocks = (n_cnt + 255) / 256;  // 391

    k_histsetup<<<eb, 256>>>(ei, W1, b1, W2, e_cnt);
    k_scan<<<sb_blocks, 256>>>(n_cnt);
    k_scatter<<<eb, 256>>>(ei, attr, e_cnt);
    k_mega<<<(n_cnt + 7) / 8, 256>>>(x, a, b, g1, g2, bias, W1, b1, W2, b2, out, n_cnt);
}

// round 6
// speedup vs baseline: 1.5296x; 1.1643x over previous
#include <cuda_runtime.h>
#include <math.h>

#define NN 100000
#define EE 3200000
#define HH 20
#define EHID 64
#define EOUT 10
#define SCANB 512   // max scan blocks

// ---- device scratch (static; zero-initialized at module load) ----
__device__ int   g_deg[NN];                 // node degree (zeroed by k_mega each call)
__device__ int   g_cnt2[NN];                // scatter cursors (zeroed by k_mega each call)
__device__ int   g_off[NN];                 // CSR exclusive offsets
__device__ unsigned long long g_flag[SCANB];// lookback flags (generation-tagged, never reset)
__device__ unsigned long long g_gen;        // generation counter
__device__ int2  g_pair[EE];                // CSR: (dst | idx<<27, dist-bits)
__device__ float g_c[EOUT];                 // collapsed MLP (b1==0): mlp_out = d*c + b2
__device__ int   g_b1zero;

// ---------------------------------------------------------------------------
// launch 1: histogram + setup + generation bump
// ---------------------------------------------------------------------------
__global__ void k_histsetup(const int* __restrict__ ei,
                            const float* __restrict__ W1,
                            const float* __restrict__ b1,
                            const float* __restrict__ W2, int e_cnt) {
    if (blockIdx.x == 0) {
        int j = threadIdx.x;
        if (j == 0) {
            g_gen = g_gen + 1;
            int z = 1;
            for (int k = 0; k < EHID; k++)
                if (b1[k] != 0.0f) { z = 0; break; }
            g_b1zero = z;
        }
        if (j < EOUT) {
            float s = 0.0f;
            for (int k = 0; k < EHID; k++) {
                float w = W1[k];
                s = fmaf(w > 0.0f ? w : 0.0f, W2[k * EOUT + j], s);
            }
            g_c[j] = s;
        }
    }
    int e = blockIdx.x * blockDim.x + threadIdx.x;
    if (e < e_cnt) atomicAdd(&g_deg[ei[e]], 1);
}

// ---------------------------------------------------------------------------
// launch 2: single-kernel exclusive scan (decoupled lookback, gen-tagged)
// ---------------------------------------------------------------------------
__global__ void __launch_bounds__(256) k_scan(int n_cnt) {
    __shared__ int s[256];
    __shared__ int sPre;
    int t = threadIdx.x, bid = blockIdx.x;
    int i = bid * 256 + t;
    int v = (i < n_cnt) ? g_deg[i] : 0;
    s[t] = v;
    __syncthreads();
#pragma unroll
    for (int o = 1; o < 256; o <<= 1) {
        int add = (t >= o) ? s[t - o] : 0;
        __syncthreads();
        s[t] += add;
        __syncthreads();
    }
    int total = s[255];

    unsigned long long gen = g_gen;
    unsigned long long wantA = gen * 4 + 1, wantP = gen * 4 + 2;

    if (t == 0) {
        unsigned long long st = (bid == 0) ? wantP : wantA;
        atomicExch(&g_flag[bid], (st << 32) | (unsigned long long)(unsigned)total);
        if (bid == 0) sPre = 0;
    }
    if (bid > 0 && t < 32) {
        int sum = 0;
        int base = bid - 1;
        for (;;) {
            int p = base - t;
            unsigned long long w = 0;
            if (p >= 0) {
                volatile unsigned long long* vp = g_flag + p;
                unsigned long long hi;
                do { w = *vp; hi = w >> 32; } while (hi != wantA && hi != wantP);
            }
            bool isP = (p >= 0) && ((w >> 32) == wantP);
            unsigned mask = __ballot_sync(0xFFFFFFFFu, isP);
            if (mask) {
                int firstP = __ffs((int)mask) - 1;
                if (t <= firstP) sum += (int)(unsigned)w;
                break;
            }
            sum += (int)(unsigned)w;   // all aggregates (p<0 lanes contribute 0)
            base -= 32;
        }
#pragma unroll
        for (int o = 16; o; o >>= 1) sum += __shfl_down_sync(0xFFFFFFFFu, sum, o);
        if (t == 0) {
            sPre = sum;
            atomicExch(&g_flag[bid],
                       (wantP << 32) | (unsigned long long)(unsigned)(sum + total));
        }
    }
    __syncthreads();
    if (i < n_cnt) g_off[i] = sPre + s[t] - v;   // global exclusive offset
}

// ---------------------------------------------------------------------------
// launch 3: scatter (dst|idx, dist) into CSR order (idx precomputed here)
// ---------------------------------------------------------------------------
__global__ void k_scatter(const int* __restrict__ ei,
                          const float* __restrict__ attr, int e_cnt) {
    int e = blockIdx.x * blockDim.x + threadIdx.x;
    if (e >= e_cnt) return;
    int src = ei[e];
    float d = attr[e];
    int idx = (int)(d * 10.0f);
    idx = idx > 9 ? 9 : idx;
    int p = g_off[src] + atomicAdd(&g_cnt2[src], 1);
    g_pair[p] = make_int2(ei[e_cnt + e] | (idx << 27), __float_as_int(d));
}

// ---------------------------------------------------------------------------
// launch 4: warp-per-node, branch-free 3-accumulator edge loop
// ---------------------------------------------------------------------------
__global__ void __launch_bounds__(256)
k_mega(const float* __restrict__ x,
       const float* __restrict__ pa, const float* __restrict__ pb,
       const float* __restrict__ g1, const float* __restrict__ g2,
       const float* __restrict__ bias,
       const float* __restrict__ W1, const float* __restrict__ b1,
       const float* __restrict__ W2, const float* __restrict__ b2,
       float* __restrict__ out, int n_cnt) {
    __shared__ float s1[HH * 21], s2[HH * 21], sb[HH];
    for (int i = threadIdx.x; i < HH * HH; i += blockDim.x) {
        int r = i / HH, cix = i % HH;
        s1[r * 21 + cix] = g1[i];
        s2[r * 21 + cix] = g2[i];
    }
    if (threadIdx.x < HH) sb[threadIdx.x] = bias[threadIdx.x];
    __syncthreads();

    const int warp = threadIdx.x >> 5;
    const int lane = threadIdx.x & 31;
    const int n = blockIdx.x * 8 + warp;
    if (n >= n_cnt) return;

    const int deg = g_deg[n];
    const int off = g_off[n];
    const float aa = __ldg(pa);
    const float bbp = __ldg(pb);
    const float oma = 1.0f - aa;
    const int bz = g_b1zero;

    const bool active = lane < HH;
    const bool isOH = lane < 10;
    const int mcol = lane - 10;

    const float x0l = active ? __ldg(x + (size_t)n * 2 * HH + lane) : 0.0f;
    const float ax0 = aa * x0l;
    const float cl  = (active && !isOH) ? g_c[mcol] : 0.0f;
    const float b2l = (active && !isOH) ? __ldg(b2 + mcol) : 0.0f;

    // unified accumulators:
    //   S = sum rho                (OH: B ; MLP: Q)
    //   T = sum rho * t            (OH: A ; MLP: P=sum rho*d)
    //   C = sum t                  (OH: cnt ; MLP: sd)
    float S = 0.0f, T = 0.0f, C = 0.0f;
    float Vs = 0.0f;   // slow path only: sum eac

    const int2* pair = g_pair + off;
    const float* xcol = x + lane;

    if (bz) {
#pragma unroll 4
        for (int i = 0; i < deg; i++) {
            int2 pr = pair[i];
            float d = __int_as_float(pr.y);
            int dst = pr.x & 0x07FFFFFF;
            float m = (((unsigned)pr.x >> 27) == (unsigned)lane) ? 1.0f : 0.0f;
            float t = isOH ? m : d;
            float xr = active ? __ldg(xcol + (size_t)dst * 2 * HH) : 0.0f;
            float v = fabsf(fmaf(-oma, xr, ax0));
            float rho = __powf(v, bbp);
            S += rho;
            T = fmaf(rho, t, T);
            C += t;
        }
    } else {
        for (int i = 0; i < deg; i++) {
            int2 pr = pair[i];
            float d = __int_as_float(pr.y);
            int dst = pr.x & 0x07FFFFFF;
            float m = (((unsigned)pr.x >> 27) == (unsigned)lane) ? 1.0f : 0.0f;
            float xr = active ? __ldg(xcol + (size_t)dst * 2 * HH) : 0.0f;
            float v = fabsf(fmaf(-oma, xr, ax0));
            float rho = __powf(v, bbp);
            float eac = b2l;
            for (int k = 0; k < EHID; k++) {
                float h = fmaf(d, __ldg(W1 + k), __ldg(b1 + k));
                h = h > 0.0f ? h : 0.0f;
                eac = fmaf(h, __ldg(W2 + k * EOUT + mcol), eac);
            }
            float t = isOH ? m : eac;   // slow path: T = sum rho*eac, C unused for mlp
            S += rho;
            T = fmaf(rho, t, T);
            C += isOH ? m : 0.0f;
            Vs += eac;
        }
    }

    // finalize this lane's sum_features column
    float num, den;
    if (bz) {
        num = isOH ? T : fmaf(cl, T, b2l * S);
        den = isOH ? C : fmaf(cl, C, b2l * (float)deg);
    } else {
        num = T;
        den = isOH ? C : Vs;
    }
    float sf = (den != 0.0f) ? num * __fdividef(1.0f, den) : 0.01f * S;

    float* o = out + (size_t)n * 2 * HH;
    if (active) o[HH + lane] = sf;               // out[n,1,:]

    // node update: out[n,0,i] = sigmoid(g1[i,:]·x0 + g2[i,:]·sf + bias[i])
    int li = active ? lane : 0;
    float acc = active ? sb[li] : 0.0f;
#pragma unroll
    for (int j = 0; j < HH; j++) {
        float bx = __shfl_sync(0xFFFFFFFFu, x0l, j);
        float bs = __shfl_sync(0xFFFFFFFFu, sf, j);
        acc = fmaf(s1[li * 21 + j], bx, acc);
        acc = fmaf(s2[li * 21 + j], bs, acc);
    }
    if (active) o[lane] = __fdividef(1.0f, 1.0f + __expf(-acc));

    // restore scratch invariant for the next execution
    if (lane == 0) {
        g_deg[n] = 0;
        g_cnt2[n] = 0;
    }
}

// ---------------------------------------------------------------------------
extern "C" void kernel_launch(void* const* d_in, const int* in_sizes, int n_in,
                              void* d_out, int out_size) {
    const float* x    = (const float*)d_in[0];
    const int*   ei   = (const int*)d_in[1];
    const float* attr = (const float*)d_in[2];
    const float* a    = (const float*)d_in[3];
    const float* b    = (const float*)d_in[4];
    const float* g1   = (const float*)d_in[5];
    const float* g2   = (const float*)d_in[6];
    const float* bias = (const float*)d_in[7];
    const float* W1   = (const float*)d_in[8];
    const float* b1   = (const float*)d_in[9];
    const float* W2   = (const float*)d_in[10];
    const float* b2   = (const float*)d_in[11];

    int e_cnt = in_sizes[1] / 2;          // edge_index is [2, E]
    int n_cnt = in_sizes[0] / (2 * HH);   // x is [N, 2, H]
    float* out = (float*)d_out;

    int eb = (e_cnt + 255) / 256;
    int sb_blocks = (n_cnt + 255) / 256;

    k_histsetup<<<eb, 256>>>(ei, W1, b1, W2, e_cnt);
    k_scan<<<sb_blocks, 256>>>(n_cnt);
    k_scatter<<<eb, 256>>>(ei, attr, e_cnt);
    k_mega<<<(n_cnt + 7) / 8, 256>>>(x, a, b, g1, g2, bias, W1, b1, W2, b2, out, n_cnt);
}

// round 7
// speedup vs baseline: 1.5986x; 1.0451x over previous
#include <cuda_runtime.h>
#include <math.h>

#define NN 100000
#define EE 3200000
#define HH 20
#define EHID 64
#define EOUT 10
#define SCANB 512   // max scan blocks

// ---- device scratch (static; zero-initialized at module load) ----
__device__ int   g_deg[NN];                 // node degree (zeroed by k_mega each call)
__device__ int   g_cnt2[NN];                // scatter cursors (zeroed by k_mega each call)
__device__ int   g_off[NN];                 // CSR exclusive offsets
__device__ unsigned long long g_flag[SCANB];// lookback flags (generation-tagged, never reset)
__device__ unsigned long long g_gen;        // generation counter
__device__ int2  g_pair[EE];                // CSR: (dst | idx<<27, dist-bits)
__device__ float g_c[EOUT];                 // collapsed MLP (b1==0): mlp_out = d*c + b2
__device__ int   g_b1zero;

// ---------------------------------------------------------------------------
// launch 1: histogram + setup + generation bump
// ---------------------------------------------------------------------------
__global__ void k_histsetup(const int* __restrict__ ei,
                            const float* __restrict__ W1,
                            const float* __restrict__ b1,
                            const float* __restrict__ W2, int e_cnt) {
    if (blockIdx.x == 0) {
        int j = threadIdx.x;
        if (j == 0) {
            g_gen = g_gen + 1;
            int z = 1;
            for (int k = 0; k < EHID; k++)
                if (b1[k] != 0.0f) { z = 0; break; }
            g_b1zero = z;
        }
        if (j < EOUT) {
            float s = 0.0f;
            for (int k = 0; k < EHID; k++) {
                float w = W1[k];
                s = fmaf(w > 0.0f ? w : 0.0f, W2[k * EOUT + j], s);
            }
            g_c[j] = s;
        }
    }
    int e = blockIdx.x * blockDim.x + threadIdx.x;
    if (e < e_cnt) atomicAdd(&g_deg[ei[e]], 1);
}

// ---------------------------------------------------------------------------
// launch 2: single-kernel exclusive scan (decoupled lookback, gen-tagged)
// ---------------------------------------------------------------------------
__global__ void __launch_bounds__(256) k_scan(int n_cnt) {
    __shared__ int s[256];
    __shared__ int sPre;
    int t = threadIdx.x, bid = blockIdx.x;
    int i = bid * 256 + t;
    int v = (i < n_cnt) ? g_deg[i] : 0;
    s[t] = v;
    __syncthreads();
#pragma unroll
    for (int o = 1; o < 256; o <<= 1) {
        int add = (t >= o) ? s[t - o] : 0;
        __syncthreads();
        s[t] += add;
        __syncthreads();
    }
    int total = s[255];

    unsigned long long gen = g_gen;
    unsigned long long wantA = gen * 4 + 1, wantP = gen * 4 + 2;

    if (t == 0) {
        unsigned long long st = (bid == 0) ? wantP : wantA;
        atomicExch(&g_flag[bid], (st << 32) | (unsigned long long)(unsigned)total);
        if (bid == 0) sPre = 0;
    }
    if (bid > 0 && t < 32) {
        int sum = 0;
        int base = bid - 1;
        for (;;) {
            int p = base - t;
            unsigned long long w = 0;
            if (p >= 0) {
                volatile unsigned long long* vp = g_flag + p;
                unsigned long long hi;
                do { w = *vp; hi = w >> 32; } while (hi != wantA && hi != wantP);
            }
            bool isP = (p >= 0) && ((w >> 32) == wantP);
            unsigned mask = __ballot_sync(0xFFFFFFFFu, isP);
            if (mask) {
                int firstP = __ffs((int)mask) - 1;
                if (t <= firstP) sum += (int)(unsigned)w;
                break;
            }
            sum += (int)(unsigned)w;
            base -= 32;
        }
#pragma unroll
        for (int o = 16; o; o >>= 1) sum += __shfl_down_sync(0xFFFFFFFFu, sum, o);
        if (t == 0) {
            sPre = sum;
            atomicExch(&g_flag[bid],
                       (wantP << 32) | (unsigned long long)(unsigned)(sum + total));
        }
    }
    __syncthreads();
    if (i < n_cnt) g_off[i] = sPre + s[t] - v;
}

// ---------------------------------------------------------------------------
// launch 3: scatter (dst|idx, dist) into CSR order (idx precomputed here)
// ---------------------------------------------------------------------------
__global__ void k_scatter(const int* __restrict__ ei,
                          const float* __restrict__ attr, int e_cnt) {
    int e = blockIdx.x * blockDim.x + threadIdx.x;
    if (e >= e_cnt) return;
    int src = ei[e];
    float d = attr[e];
    int idx = (int)(d * 10.0f);
    idx = idx > 9 ? 9 : idx;
    int p = g_off[src] + atomicAdd(&g_cnt2[src], 1);
    g_pair[p] = make_int2(ei[e_cnt + e] | (idx << 27), __float_as_int(d));
}

// ---------------------------------------------------------------------------
// launch 4: dense packing — warp = 8 nodes, 4 lanes/node, 5 columns/lane
// ---------------------------------------------------------------------------
__global__ void __launch_bounds__(256)
k_mega(const float* __restrict__ x,
       const float* __restrict__ pa, const float* __restrict__ pb,
       const float* __restrict__ g1, const float* __restrict__ g2,
       const float* __restrict__ bias,
       const float* __restrict__ W1, const float* __restrict__ b1,
       const float* __restrict__ W2, const float* __restrict__ b2,
       float* __restrict__ out, int n_cnt) {
    __shared__ float s1[HH * 21], s2[HH * 21], sb[HH];
    __shared__ float sfs[64][21];   // per-block node sf rows (pad 21)
    __shared__ float x0s[64][21];   // per-block node x0 rows
    for (int i = threadIdx.x; i < HH * HH; i += 256) {
        int r = i / HH, cix = i % HH;
        s1[r * 21 + cix] = g1[i];
        s2[r * 21 + cix] = g2[i];
    }
    if (threadIdx.x < HH) sb[threadIdx.x] = bias[threadIdx.x];
    __syncthreads();

    const int warp = threadIdx.x >> 5;
    const int lane = threadIdx.x & 31;
    const int g = lane >> 2;          // node slot within warp (0..7)
    const int q = lane & 3;           // column group (0..3)
    const int colbase = q * 5;
    const bool isOH = q < 2;          // cols 0-9 one-hot, 10-19 mlp
    const int nl = warp * 8 + g;      // node local to block (0..63)
    const int n = blockIdx.x * 64 + nl;
    const bool nvalid = n < n_cnt;

    const int deg = nvalid ? g_deg[n] : 0;
    const int off = nvalid ? g_off[n] : 0;
    const float aa = __ldg(pa);
    const float bbp = __ldg(pb);
    const float oma = 1.0f - aa;
    const int bz = g_b1zero;

    // node's own columns (5 per lane), stash x0 to smem for the epilogue
    float ax0[5];
    {
        const float* xrow = x + (size_t)n * 2 * HH + colbase;
#pragma unroll
        for (int c = 0; c < 5; c++) {
            float xv = nvalid ? __ldg(xrow + c) : 0.0f;
            ax0[c] = aa * xv;
            x0s[nl][colbase + c] = xv;
        }
    }

    // per-column accumulators: S=sum rho, T=sum rho*t, C=sum t
    float S[5], T[5], C[5];
#pragma unroll
    for (int c = 0; c < 5; c++) { S[c] = 0.0f; T[c] = 0.0f; C[c] = 0.0f; }

    const int mdeg = __reduce_max_sync(0xFFFFFFFFu, deg);
    const int2* pair = g_pair + off;
    const float* xb = x + colbase;

    if (bz) {
        for (int i = 0; i < mdeg; i++) {
            const bool act = i < deg;
            int2 pr = act ? pair[i] : make_int2(0, __float_as_int(0.0f));
            float d = __int_as_float(pr.y);
            unsigned idxv = (unsigned)pr.x >> 27;
            int dst = pr.x & 0x07FFFFFF;
            float f0 = isOH ? 0.0f : d;
            const float* xr = xb + (size_t)dst * 2 * HH;
#pragma unroll
            for (int c = 0; c < 5; c++) {
                float xv = act ? __ldg(xr + c) : 0.0f;
                float v = fabsf(fmaf(-oma, xv, ax0[c]));
                float rho = __powf(v, bbp);
                float t = (idxv == (unsigned)(colbase + c)) ? 1.0f : f0;
                if (act) {
                    S[c] += rho;
                    T[c] = fmaf(rho, t, T[c]);
                    C[c] += t;
                }
            }
        }
    } else {
        // slow fallback (b1 != 0): per-edge MLP; t = eac for mlp cols,
        // so C accumulates sum(eac) and den=C works for both families.
        const int mb = isOH ? 0 : (colbase - 10);
        float b2v[5];
#pragma unroll
        for (int c = 0; c < 5; c++) b2v[c] = isOH ? 0.0f : __ldg(b2 + mb + c);
        for (int i = 0; i < mdeg; i++) {
            const bool act = i < deg;
            int2 pr = act ? pair[i] : make_int2(0, __float_as_int(0.0f));
            float d = __int_as_float(pr.y);
            unsigned idxv = (unsigned)pr.x >> 27;
            int dst = pr.x & 0x07FFFFFF;
            float eac[5];
#pragma unroll
            for (int c = 0; c < 5; c++) eac[c] = b2v[c];
            for (int k = 0; k < EHID; k++) {
                float h = fmaf(d, __ldg(W1 + k), __ldg(b1 + k));
                h = h > 0.0f ? h : 0.0f;
#pragma unroll
                for (int c = 0; c < 5; c++)
                    eac[c] = fmaf(h, __ldg(W2 + k * EOUT + mb + c), eac[c]);
            }
            const float* xr = xb + (size_t)dst * 2 * HH;
#pragma unroll
            for (int c = 0; c < 5; c++) {
                float xv = act ? __ldg(xr + c) : 0.0f;
                float v = fabsf(fmaf(-oma, xv, ax0[c]));
                float rho = __powf(v, bbp);
                float f0 = isOH ? 0.0f : eac[c];
                float t = (idxv == (unsigned)(colbase + c)) ? 1.0f : f0;
                if (act) {
                    S[c] += rho;
                    T[c] = fmaf(rho, t, T[c]);
                    C[c] += t;
                }
            }
        }
    }

    // finalize this lane's 5 sum_features columns
    {
        const int mb = isOH ? 0 : (colbase - 10);
        float* orow = out + (size_t)n * 2 * HH + HH + colbase;
#pragma unroll
        for (int c = 0; c < 5; c++) {
            float num, den;
            if (bz) {
                float clv = isOH ? 0.0f : g_c[mb + c];
                float b2l = isOH ? 0.0f : __ldg(b2 + mb + c);
                num = isOH ? T[c] : fmaf(clv, T[c], b2l * S[c]);
                den = isOH ? C[c] : fmaf(clv, C[c], b2l * (float)deg);
            } else {
                num = T[c];
                den = C[c];
            }
            float sf = (den != 0.0f) ? num * __fdividef(1.0f, den) : 0.01f * S[c];
            sfs[nl][colbase + c] = sf;
            if (nvalid) orow[c] = sf;          // out[n,1,:]
        }
    }

    // restore scratch invariant
    if (q == 0 && nvalid) { g_deg[n] = 0; g_cnt2[n] = 0; }

    __syncwarp();

    // epilogue: node update for this warp's 8 nodes (160 outputs, 5 rounds)
    const int wbase = warp * 8;
#pragma unroll
    for (int r = 0; r < 5; r++) {
        int oi = r * 32 + lane;           // 0..159
        int dn = oi / 20;                 // 0..7
        int i = oi - dn * 20;
        int nl2 = wbase + dn;
        int gn = blockIdx.x * 64 + nl2;
        float acc = sb[i];
#pragma unroll
        for (int j = 0; j < HH; j++) {
            acc = fmaf(s1[i * 21 + j], x0s[nl2][j], acc);
            acc = fmaf(s2[i * 21 + j], sfs[nl2][j], acc);
        }
        if (gn < n_cnt)
            out[(size_t)gn * 2 * HH + i] = __fdividef(1.0f, 1.0f + __expf(-acc));
    }
}

// ---------------------------------------------------------------------------
extern "C" void kernel_launch(void* const* d_in, const int* in_sizes, int n_in,
                              void* d_out, int out_size) {
    const float* x    = (const float*)d_in[0];
    const int*   ei   = (const int*)d_in[1];
    const float* attr = (const float*)d_in[2];
    const float* a    = (const float*)d_in[3];
    const float* b    = (const float*)d_in[4];
    const float* g1   = (const float*)d_in[5];
    const float* g2   = (const float*)d_in[6];
    const float* bias = (const float*)d_in[7];
    const float* W1   = (const float*)d_in[8];
    const float* b1   = (const float*)d_in[9];
    const float* W2   = (const float*)d_in[10];
    const float* b2   = (const float*)d_in[11];

    int e_cnt = in_sizes[1] / 2;          // edge_index is [2, E]
    int n_cnt = in_sizes[0] / (2 * HH);   // x is [N, 2, H]
    float* out = (float*)d_out;

    int eb = (e_cnt + 255) / 256;
    int sb_blocks = (n_cnt + 255) / 256;

    k_histsetup<<<eb, 256>>>(ei, W1, b1, W2, e_cnt);
    k_scan<<<sb_blocks, 256>>>(n_cnt);
    k_scatter<<<eb, 256>>>(ei, attr, e_cnt);
    k_mega<<<(n_cnt + 63) / 64, 256>>>(x, a, b, g1, g2, bias, W1, b1, W2, b2, out, n_cnt);
}